// round 10
// baseline (speedup 1.0000x reference)
#include <cuda_runtime.h>

#define BB 32
#define SS 512
#define LL 64
#define TSTART 61
#define TSTOP 62

typedef unsigned long long ull;

__device__ __forceinline__ ull fma2(ull a, ull b, ull c) {
    ull d; asm("fma.rn.f32x2 %0, %1, %2, %3;" : "=l"(d) : "l"(a), "l"(b), "l"(c)); return d;
}
__device__ __forceinline__ ull mul2(ull a, ull b) {
    ull d; asm("mul.rn.f32x2 %0, %1, %2;" : "=l"(d) : "l"(a), "l"(b)); return d;
}
__device__ __forceinline__ ull add2(ull a, ull b) {
    ull d; asm("add.rn.f32x2 %0, %1, %2;" : "=l"(d) : "l"(a), "l"(b)); return d;
}
__device__ __forceinline__ ull pack2(float lo, float hi) {
    ull d; asm("mov.b64 %0, {%1, %2};" : "=l"(d) : "r"(__float_as_uint(lo)), "r"(__float_as_uint(hi))); return d;
}
__device__ __forceinline__ float2 unpack2(ull v) {
    unsigned lo, hi; asm("mov.b64 {%0, %1}, %2;" : "=r"(lo), "=r"(hi) : "l"(v));
    return make_float2(__uint_as_float(lo), __uint_as_float(hi));
}

// Single-warp scan step. Lane l owns states (2l, 2l+1), value pair u2.
// Wlo[m]/Whi[m] = weight pairs over input-state pair m for the two owned states.
// Exchange is intra-warp: STS.64 + __syncwarp only (no block barrier).
// REN: uniform rescale by published p_prev[0] (always finite & positive).
template<bool REN>
__device__ __forceinline__ ull step32(ull u2, ull f2, float* spb,
                                      const ull* __restrict__ Wlo,
                                      const ull* __restrict__ Whi,
                                      int l, float& C) {
    ((ull*)spb)[l] = u2;                 // STS.64
    __syncwarp(0xffffffffu);
    const ulonglong2* sp2 = (const ulonglong2*)spb;   // 16 x 16B broadcast reads
    ull a0, a1, a2, a3, b0, b1, b2, b3;
    {
        const ulonglong2 v = sp2[0], w = sp2[8];
        a0 = mul2(v.x, Wlo[0]);  a1 = mul2(v.y, Wlo[1]);
        a2 = mul2(w.x, Wlo[16]); a3 = mul2(w.y, Wlo[17]);
        b0 = mul2(v.x, Whi[0]);  b1 = mul2(v.y, Whi[1]);
        b2 = mul2(w.x, Whi[16]); b3 = mul2(w.y, Whi[17]);
    }
    #pragma unroll
    for (int k = 1; k < 8; k++) {
        const ulonglong2 v = sp2[k], w = sp2[k + 8];
        a0 = fma2(v.x, Wlo[2*k],      a0); a1 = fma2(v.y, Wlo[2*k + 1],  a1);
        a2 = fma2(w.x, Wlo[2*k + 16], a2); a3 = fma2(w.y, Wlo[2*k + 17], a3);
        b0 = fma2(v.x, Whi[2*k],      b0); b1 = fma2(v.y, Whi[2*k + 1],  b1);
        b2 = fma2(w.x, Whi[2*k + 16], b2); b3 = fma2(w.y, Whi[2*k + 17], b3);
    }
    const float2 ta = unpack2(add2(add2(a0, a1), add2(a2, a3)));
    const float2 tb = unpack2(add2(add2(b0, b1), add2(b2, b3)));
    const ull dots = pack2(ta.x + ta.y, tb.x + tb.y);
    if (REN) {
        const float v0 = spb[0];         // uniform across the warp
        C += __logf(v0);
        const float r = __fdividef(1.0f, v0);
        return mul2(mul2(dots, f2), pack2(r, r));
    }
    return mul2(dots, f2);
}

__global__ __launch_bounds__(64, 1)
void crf_kernel(const float* __restrict__ enc,     // [B,S,L]
                const float* __restrict__ trans,   // [L,L]
                const int*   __restrict__ lens,    // [B]
                const int*   __restrict__ tags,    // [B,S]
                float*       __restrict__ out)     // [2*B]
{
    __shared__ float spbufF[2][LL];
    __shared__ float spbufB[2][LL];
    __shared__ float sP[LL], sQ[LL];
    __shared__ float sC[2];
    __shared__ float sred[2];
    const int tid = threadIdx.x;

    if (blockIdx.x < BB) {
        // ===== scan block: warp0 = forward half, warp1 = backward half =====
        const int b = blockIdx.x;
        const int w = tid >> 5;
        const int l = tid & 31;
        const int len = lens[b];
        const int m = (len + 1) >> 1;
        const float*  encb = enc + (size_t)b * SS * LL;
        const float2* encp = (const float2*)encb;      // encp[t*32 + l] = enc[t][2l..2l+1]

        float C = 0.0f;
        ull Wlo[32], Whi[32];

        if (w == 0) {
            // ---------- forward: p_0 .. p_{m-1} ----------
            #pragma unroll
            for (int i = 0; i < 32; i++) {
                Wlo[i] = pack2(__expf(trans[(2*i)     * LL + 2*l]),
                               __expf(trans[(2*i + 1) * LL + 2*l]));
                Whi[i] = pack2(__expf(trans[(2*i)     * LL + 2*l + 1]),
                               __expf(trans[(2*i + 1) * LL + 2*l + 1]));
            }
            ull u2 = pack2(__expf(trans[TSTART * LL + 2*l]     + encb[2*l]),
                           __expf(trans[TSTART * LL + 2*l + 1] + encb[2*l + 1]));

            const int N = m - 1;
            ull fq[4];
            #pragma unroll
            for (int k0 = 0; k0 < 4; k0++) {
                const float2 e = encp[min(1 + k0, N) * 32 + l];
                fq[k0] = pack2(__expf(e.x), __expf(e.y));
            }

            int k = 1;
            for (; k + 3 <= N; k += 4) {
                float2 er[4];
                #pragma unroll
                for (int k0 = 0; k0 < 4; k0++)
                    er[k0] = encp[min(k + 4 + k0, N) * 32 + l];
                u2 = step32<false>(u2, fq[0], spbufF[(k    ) & 1], Wlo, Whi, l, C);
                u2 = step32<false>(u2, fq[1], spbufF[(k + 1) & 1], Wlo, Whi, l, C);
                u2 = step32<false>(u2, fq[2], spbufF[(k + 2) & 1], Wlo, Whi, l, C);
                u2 = step32<true >(u2, fq[3], spbufF[(k + 3) & 1], Wlo, Whi, l, C);
                #pragma unroll
                for (int k0 = 0; k0 < 4; k0++)
                    fq[k0] = pack2(__expf(er[k0].x), __expf(er[k0].y));
            }
            #pragma unroll
            for (int k0 = 0; k0 < 3; k0++) {
                if (k + k0 <= N) {
                    if (((k + k0) & 3) == 0)
                        u2 = step32<true >(u2, fq[k0], spbufF[(k + k0) & 1], Wlo, Whi, l, C);
                    else
                        u2 = step32<false>(u2, fq[k0], spbufF[(k + k0) & 1], Wlo, Whi, l, C);
                }
            }
            ((ull*)sP)[l] = u2;           // p_{m-1}
            if (l == 0) sC[0] = C;
        } else {
            // ---------- backward: publishes v_t = f_t*q_t; q_{t-1} = E v_t ----------
            #pragma unroll
            for (int i = 0; i < 32; i++) {
                Wlo[i] = pack2(__expf(trans[(2*l)     * LL + 2*i]),
                               __expf(trans[(2*l)     * LL + 2*i + 1]));
                Whi[i] = pack2(__expf(trans[(2*l + 1) * LL + 2*i]),
                               __expf(trans[(2*l + 1) * LL + 2*i + 1]));
            }
            ull u2 = pack2(__expf(trans[(2*l)     * LL + TSTOP] + encb[(size_t)(len - 1) * LL + 2*l]),
                           __expf(trans[(2*l + 1) * LL + TSTOP] + encb[(size_t)(len - 1) * LL + 2*l + 1]));

            const int Nb = len - m;       // total steps; last one has f = 1
            const int Ng = Nb - 1;
            ull fq[4];
            #pragma unroll
            for (int k0 = 0; k0 < 4; k0++) {
                const float2 e = encp[(len - 1 - min(1 + k0, Ng)) * 32 + l];
                fq[k0] = pack2(__expf(e.x), __expf(e.y));
            }

            int k = 1;
            for (; k + 3 <= Ng; k += 4) {
                float2 er[4];
                #pragma unroll
                for (int k0 = 0; k0 < 4; k0++)
                    er[k0] = encp[(len - 1 - min(k + 4 + k0, Ng)) * 32 + l];
                u2 = step32<false>(u2, fq[0], spbufB[(k    ) & 1], Wlo, Whi, l, C);
                u2 = step32<false>(u2, fq[1], spbufB[(k + 1) & 1], Wlo, Whi, l, C);
                u2 = step32<false>(u2, fq[2], spbufB[(k + 2) & 1], Wlo, Whi, l, C);
                u2 = step32<true >(u2, fq[3], spbufB[(k + 3) & 1], Wlo, Whi, l, C);
                #pragma unroll
                for (int k0 = 0; k0 < 4; k0++)
                    fq[k0] = pack2(__expf(er[k0].x), __expf(er[k0].y));
            }
            #pragma unroll
            for (int k0 = 0; k0 < 3; k0++) {
                if (k + k0 <= Ng) {
                    if (((k + k0) & 3) == 0)
                        u2 = step32<true >(u2, fq[k0], spbufB[(k + k0) & 1], Wlo, Whi, l, C);
                    else
                        u2 = step32<false>(u2, fq[k0], spbufB[(k + k0) & 1], Wlo, Whi, l, C);
                }
            }
            // final step, f = 1: produces q_{m-1}
            const ull one2 = pack2(1.0f, 1.0f);
            u2 = step32<false>(u2, one2, spbufB[Nb & 1], Wlo, Whi, l, C);
            ((ull*)sQ)[l] = u2;
            if (l == 0) sC[1] = C;
        }

        __syncthreads();
        // out[b] = C_f + C_b + log( sum_j p_{m-1}[j] * q_{m-1}[j] )
        if (tid < 32) {
            const float2 p2 = ((const float2*)sP)[tid];
            const float2 q2 = ((const float2*)sQ)[tid];
            float v = p2.x * q2.x + p2.y * q2.y;
            #pragma unroll
            for (int off = 16; off; off >>= 1)
                v += __shfl_xor_sync(0xffffffffu, v, off);
            if (tid == 0) out[b] = sC[0] + sC[1] + __logf(v);
        }
    } else {
        // ================= labeled path score =================
        const int b = blockIdx.x - BB;
        const int len = lens[b];
        const float* encb = enc + (size_t)b * SS * LL;
        const int* tg = tags + b * SS;

        float acc = 0.f;
        for (int t = 1 + tid; t < len; t += 64) {
            const int tt = tg[t];
            const int tp = tg[t - 1];
            acc += trans[tp * LL + tt] + encb[t * LL + tt];
        }
        #pragma unroll
        for (int off = 16; off; off >>= 1)
            acc += __shfl_xor_sync(0xffffffffu, acc, off);
        if ((tid & 31) == 0) sred[tid >> 5] = acc;
        __syncthreads();
        if (tid == 0) {
            const int t0 = tg[0];
            const float begin = trans[TSTART * LL + t0] + encb[t0];
            const float endsc = trans[tg[len - 1] * LL + TSTOP];
            out[BB + b] = sred[0] + sred[1] + begin + endsc;
        }
    }
}

extern "C" void kernel_launch(void* const* d_in, const int* in_sizes, int n_in,
                              void* d_out, int out_size) {
    const float* enc   = (const float*)d_in[0];   // encoder_scores [32,512,64]
    const float* trans = (const float*)d_in[1];   // transition [64,64]
    const int*   lens  = (const int*)d_in[2];     // word_seq_lens [32]
    const int*   tags  = (const int*)d_in[3];     // tags [32,512]
    // d_in[4] = mask: unused (recomputed from lens)
    float* out = (float*)d_out;                   // [64] = unlabeled(32) ++ labeled(32)
    (void)in_sizes; (void)n_in; (void)out_size;

    crf_kernel<<<2 * BB, 64>>>(enc, trans, lens, tags, out);
}